// round 9
// baseline (speedup 1.0000x reference)
#include <cuda_runtime.h>
#include <math.h>

// Shapes (fixed by the problem)
#define NN 2048      // nodes
#define BB 32        // batch
#define TT 12        // time steps
#define DD 10        // embed dim
#define HH 32        // hidden
#define CH 33        // C + H
#define OG 64        // 2H (gate out)
#define BH (BB*HH)       // 1024 columns for state GEMMs
#define NCS (BB*TT)      // 384 columns for source GEMM
#define WGSZ (2*CH*OG)   // 4224
#define WUSZ (2*CH*HH)   // 2112

// ---------------- device scratch (static: allocation-free contract) ----------------
__device__ float g_A   [NN*NN];       // adjacency, row-softmaxed           16.8 MB
__device__ float g_Wg  [NN*WGSZ];     // per-node gate weights              34.6 MB
__device__ float g_bg  [NN*OG];
__device__ float g_Wu  [NN*WUSZ];     // per-node update weights            17.3 MB
__device__ float g_bu  [NN*HH];
__device__ float g_Xs  [NN*NCS];      // src transposed [m][t*32+b]          3 MB
__device__ float g_AX  [NN*NCS];      // A @ src                             3 MB
__device__ float g_H   [NN*BH];       // state  [n][b*32+h]                  8 MB
__device__ float g_Y   [NN*BH];       // A @ H                               8 MB
__device__ float g_ZH  [NN*BH];       // z * H                               8 MB
__device__ float g_Y2  [NN*BH];       // A @ ZH                              8 MB
__device__ float g_R   [NN*BH];       // reset gate r                        8 MB

// ---------------- A = softmax(relu(E E^T)) : one block per row ----------------
__global__ __launch_bounds__(256) void adj_kernel(const float* __restrict__ E) {
    const int n = blockIdx.x;
    const int tid = threadIdx.x;
    __shared__ float sE[DD];
    __shared__ float red[256];
    if (tid < DD) sE[tid] = E[n*DD + tid];
    __syncthreads();

    float v[8];
    float mx = 0.0f;   // relu outputs are >= 0
    #pragma unroll
    for (int p = 0; p < 8; ++p) {
        const int m = tid + p*256;
        float s = 0.f;
        #pragma unroll
        for (int d = 0; d < DD; ++d) s += sE[d] * E[m*DD + d];
        s = fmaxf(s, 0.0f);
        v[p] = s;
        mx = fmaxf(mx, s);
    }
    red[tid] = mx; __syncthreads();
    for (int off = 128; off; off >>= 1) {
        if (tid < off) red[tid] = fmaxf(red[tid], red[tid+off]);
        __syncthreads();
    }
    mx = red[0];
    __syncthreads();
    float sum = 0.f;
    #pragma unroll
    for (int p = 0; p < 8; ++p) { v[p] = expf(v[p] - mx); sum += v[p]; }
    red[tid] = sum; __syncthreads();
    for (int off = 128; off; off >>= 1) {
        if (tid < off) red[tid] += red[tid+off];
        __syncthreads();
    }
    const float inv = 1.0f / red[0];
    #pragma unroll
    for (int p = 0; p < 8; ++p) g_A[n*NN + tid + p*256] = v[p] * inv;
}

// ---------------- out[n*R + r] = sum_d E[n,d] * pool[d*R + r] ----------------
__global__ void expand_kernel(const float* __restrict__ pool, const float* __restrict__ E,
                              float* __restrict__ outp, int R) {
    const int total = NN * R;
    for (int idx = blockIdx.x*blockDim.x + threadIdx.x; idx < total;
         idx += gridDim.x*blockDim.x) {
        const int n = idx / R;
        const int r = idx - n*R;
        float s = 0.f;
        #pragma unroll
        for (int d = 0; d < DD; ++d) s += E[n*DD + d] * pool[d*R + r];
        outp[idx] = s;
    }
}

// ---------------- transpose src -> Xs[m][t*32+b] ----------------
__global__ void xpose_kernel(const float* __restrict__ src) {
    const int total = NN * NCS;
    for (int idx = blockIdx.x*blockDim.x + threadIdx.x; idx < total;
         idx += gridDim.x*blockDim.x) {
        const int m = idx / NCS;
        const int j = idx - m*NCS;
        const int t = j >> 5;
        const int b = j & 31;
        g_Xs[idx] = src[(b*TT + t)*NN + m];
    }
}

// ---------------- zero H, Y, Y2 ----------------
__global__ void zero3_kernel() {
    const int total = NN*BH;
    for (int i = blockIdx.x*blockDim.x + threadIdx.x; i < total;
         i += gridDim.x*blockDim.x) {
        g_H[i] = 0.f; g_Y[i] = 0.f; g_Y2[i] = 0.f;
    }
}

// ---------------- SGEMM: C[2048 x ncols] = A[2048 x 2048] * B[2048 x ncols] ----------------
// 128x64 tile, BK=16, 256 threads, 8x4 micro-tile, register prefetch.
#define BM 128
#define BN 64
#define BK 16
__global__ __launch_bounds__(256) void sgemm_kernel(const float* __restrict__ A,
                                                    const float* __restrict__ B,
                                                    float* __restrict__ C, int ncols) {
    __shared__ __align__(16) float As[BK][BM+4];   // +4 pad: conflict-lite transposed store
    __shared__ __align__(16) float Bs[BK][BN];
    const int bm = blockIdx.y * BM;
    const int bn = blockIdx.x * BN;
    const int tid = threadIdx.x;

    const int arow = tid >> 2;            // 0..63
    const int acol = (tid & 3) << 2;      // 0,4,8,12
    const int brow = tid >> 4;            // 0..15
    const int bcol = (tid & 15) << 2;     // 0..60
    const int tm   = (tid >> 4) << 3;     // 0..120
    const int tn   = (tid & 15) << 2;     // 0..60

    const float* Ap0 = A + (bm + arow)*NN + acol;
    const float* Ap1 = Ap0 + 64*NN;
    const float* Bp  = B + brow*ncols + bn + bcol;

    float4 pa0 = *(const float4*)(Ap0);
    float4 pa1 = *(const float4*)(Ap1);
    float4 pb  = *(const float4*)(Bp);

    float acc[8][4] = {};

    for (int k0 = 0; k0 < NN; k0 += BK) {
        // commit prefetched tile to smem
        As[acol+0][arow]    = pa0.x; As[acol+1][arow]    = pa0.y;
        As[acol+2][arow]    = pa0.z; As[acol+3][arow]    = pa0.w;
        As[acol+0][arow+64] = pa1.x; As[acol+1][arow+64] = pa1.y;
        As[acol+2][arow+64] = pa1.z; As[acol+3][arow+64] = pa1.w;
        *(float4*)(&Bs[brow][bcol]) = pb;
        __syncthreads();

        if (k0 + BK < NN) {     // prefetch next tile while computing
            pa0 = *(const float4*)(Ap0 + k0 + BK);
            pa1 = *(const float4*)(Ap1 + k0 + BK);
            pb  = *(const float4*)(Bp + (k0 + BK)*ncols);
        }

        #pragma unroll
        for (int k = 0; k < BK; ++k) {
            const float4 a0 = *(const float4*)(&As[k][tm]);
            const float4 a1 = *(const float4*)(&As[k][tm+4]);
            const float4 bb = *(const float4*)(&Bs[k][tn]);
            const float ar[8] = {a0.x,a0.y,a0.z,a0.w,a1.x,a1.y,a1.z,a1.w};
            const float br[4] = {bb.x,bb.y,bb.z,bb.w};
            #pragma unroll
            for (int i = 0; i < 8; ++i)
                #pragma unroll
                for (int j = 0; j < 4; ++j)
                    acc[i][j] = fmaf(ar[i], br[j], acc[i][j]);
        }
        __syncthreads();
    }

    #pragma unroll
    for (int i = 0; i < 8; ++i) {
        float4 o; o.x = acc[i][0]; o.y = acc[i][1]; o.z = acc[i][2]; o.w = acc[i][3];
        *(float4*)(C + (bm + tm + i)*ncols + bn + tn) = o;
    }
}

// ---------------- gate kernel: one block per node ----------------
// zr = sigmoid( bg[n] + sum_ii xs[ii] * Wg[n][ii][o] ),  ii folds (k,i)
// xs layout: ii=0 -> xt ; 1..32 -> h ; 33 -> A@xt ; 34..65 -> A@h
// writes ZH = z*h  (o<32)  and  R = r  (o>=32)
__global__ __launch_bounds__(256) void gate_kernel(const float* __restrict__ src, int t) {
    const int n = blockIdx.x;
    const int tid = threadIdx.x;
    __shared__ float sW[WGSZ];        // 4224 floats
    __shared__ float sxs[66*33];      // [ii][b], padded row 33
    __shared__ float sbg[OG];

    const float* Wg = g_Wg + n*WGSZ;
    for (int i = tid; i < WGSZ; i += 256) sW[i] = Wg[i];
    if (tid < OG) sbg[tid] = g_bg[n*OG + tid];
    if (tid < BB) {
        sxs[0*33 + tid]  = src[(tid*TT + t)*NN + n];            // xt
        sxs[33*33 + tid] = g_AX[n*NCS + t*BB + tid];            // A@xt
    }
    for (int j = tid; j < BH; j += 256) {
        const int b = j >> 5, hh = j & 31;
        sxs[(1+hh)*33 + b]  = g_H[n*BH + j];                    // h
        sxs[(34+hh)*33 + b] = g_Y[n*BH + j];                    // A@h
    }
    __syncthreads();

    const int o  = tid & 63;
    const int bg = tid >> 6;          // 0..3
    float acc[8];
    #pragma unroll
    for (int p = 0; p < 8; ++p) acc[p] = sbg[o];
    #pragma unroll 2
    for (int ii = 0; ii < 66; ++ii) {
        const float w = sW[ii*64 + o];
        #pragma unroll
        for (int p = 0; p < 8; ++p)
            acc[p] = fmaf(w, sxs[ii*33 + bg + p*4], acc[p]);
    }
    #pragma unroll
    for (int p = 0; p < 8; ++p) {
        const int b = bg + p*4;
        const float v = 1.0f / (1.0f + expf(-acc[p]));
        if (o < HH) g_ZH[n*BH + b*HH + o]        = v * sxs[(1+o)*33 + b];  // z * h
        else        g_R [n*BH + b*HH + (o - HH)] = v;                      // r
    }
}

// ---------------- update kernel: one block per node ----------------
// hc = tanh( bu[n] + sum_ii xu[ii] * Wu[n][ii][o] ), xu: [xt, z*h, A@xt, A@(z*h)]
// h_new = r*h + (1-r)*hc
__global__ __launch_bounds__(256) void update_kernel(const float* __restrict__ src, int t) {
    const int n = blockIdx.x;
    const int tid = threadIdx.x;
    __shared__ float sW[WUSZ];        // 2112 floats
    __shared__ float sxu[66*33];
    __shared__ float sbu[HH];

    const float* Wu = g_Wu + n*WUSZ;
    for (int i = tid; i < WUSZ; i += 256) sW[i] = Wu[i];
    if (tid < HH) sbu[tid] = g_bu[n*HH + tid];
    if (tid < BB) {
        sxu[0*33 + tid]  = src[(tid*TT + t)*NN + n];
        sxu[33*33 + tid] = g_AX[n*NCS + t*BB + tid];
    }
    for (int j = tid; j < BH; j += 256) {
        const int b = j >> 5, hh = j & 31;
        sxu[(1+hh)*33 + b]  = g_ZH[n*BH + j];
        sxu[(34+hh)*33 + b] = g_Y2[n*BH + j];
    }
    __syncthreads();

    const int o  = tid & 31;
    const int bg = tid >> 5;          // 0..7
    float acc[4];
    #pragma unroll
    for (int p = 0; p < 4; ++p) acc[p] = sbu[o];
    #pragma unroll 2
    for (int ii = 0; ii < 66; ++ii) {
        const float w = sW[ii*32 + o];
        #pragma unroll
        for (int p = 0; p < 4; ++p)
            acc[p] = fmaf(w, sxu[ii*33 + bg + p*8], acc[p]);
    }
    #pragma unroll
    for (int p = 0; p < 4; ++p) {
        const int b = bg + p*8;
        const float hc = tanhf(acc[p]);
        const int idx = n*BH + b*HH + o;
        const float r = g_R[idx];
        const float h = g_H[idx];
        g_H[idx] = r*h + (1.0f - r)*hc;
    }
}

// ---------------- output: out[b,0,n,t] = sum_h H[n][b*32+h]*convW[t,h] + convb[t] ----------------
__global__ __launch_bounds__(256) void out_kernel(const float* __restrict__ convW,
                                                  const float* __restrict__ convb,
                                                  float* __restrict__ out) {
    __shared__ float sw[TT*HH];
    __shared__ float sb[TT];
    const int tid = threadIdx.x;
    for (int i = tid; i < TT*HH; i += 256) sw[i] = convW[i];
    if (tid < TT) sb[tid] = convb[tid];
    __syncthreads();

    const int idx = blockIdx.x*256 + tid;   // 0 .. 65535  (b,n)
    const int b = idx >> 11;
    const int n = idx & (NN-1);
    float hreg[HH];
    const float4* hp = (const float4*)(g_H + n*BH + b*HH);
    #pragma unroll
    for (int q = 0; q < 8; ++q) {
        const float4 v = hp[q];
        hreg[q*4+0] = v.x; hreg[q*4+1] = v.y; hreg[q*4+2] = v.z; hreg[q*4+3] = v.w;
    }
    #pragma unroll
    for (int tt = 0; tt < TT; ++tt) {
        float s = sb[tt];
        #pragma unroll
        for (int h = 0; h < HH; ++h) s = fmaf(hreg[h], sw[tt*HH + h], s);
        out[(b*NN + n)*TT + tt] = s;
    }
}

// ---------------- launcher ----------------
extern "C" void kernel_launch(void* const* d_in, const int* in_sizes, int n_in,
                              void* d_out, int out_size) {
    (void)in_sizes; (void)n_in; (void)out_size;
    const float* src    = (const float*)d_in[0];
    const float* E      = (const float*)d_in[1];
    const float* gate_W = (const float*)d_in[2];
    const float* gate_b = (const float*)d_in[3];
    const float* upd_W  = (const float*)d_in[4];
    const float* upd_b  = (const float*)d_in[5];
    const float* conv_W = (const float*)d_in[6];
    const float* conv_b = (const float*)d_in[7];
    float* out = (float*)d_out;

    float *pA, *pXs, *pAX, *pH, *pY, *pZH, *pY2;
    float *pWg, *pbg, *pWu, *pbu;
    cudaGetSymbolAddress((void**)&pA,  g_A);
    cudaGetSymbolAddress((void**)&pXs, g_Xs);
    cudaGetSymbolAddress((void**)&pAX, g_AX);
    cudaGetSymbolAddress((void**)&pH,  g_H);
    cudaGetSymbolAddress((void**)&pY,  g_Y);
    cudaGetSymbolAddress((void**)&pZH, g_ZH);
    cudaGetSymbolAddress((void**)&pY2, g_Y2);
    cudaGetSymbolAddress((void**)&pWg, g_Wg);
    cudaGetSymbolAddress((void**)&pbg, g_bg);
    cudaGetSymbolAddress((void**)&pWu, g_Wu);
    cudaGetSymbolAddress((void**)&pbu, g_bu);

    // --- time-invariant precompute ---
    adj_kernel<<<NN, 256>>>(E);
    expand_kernel<<<2048, 256>>>(gate_W, E, pWg, WGSZ);
    expand_kernel<<<256,  256>>>(gate_b, E, pbg, OG);
    expand_kernel<<<2048, 256>>>(upd_W,  E, pWu, WUSZ);
    expand_kernel<<<256,  256>>>(upd_b,  E, pbu, HH);
    xpose_kernel<<<1024, 256>>>(src);
    zero3_kernel<<<2048, 256>>>();

    dim3 gSrc(NCS/BN, NN/BM);   // (6, 16)
    sgemm_kernel<<<gSrc, 256>>>(pA, pXs, pAX, NCS);   // AX = A @ src (all t at once)

    // --- t = 0: state is zero, so A@H = A@ZH = 0 (pre-zeroed); skip both GEMMs ---
    gate_kernel<<<NN, 256>>>(src, 0);
    update_kernel<<<NN, 256>>>(src, 0);

    dim3 gState(BH/BN, NN/BM);  // (16, 16)
    for (int t = 1; t < TT; ++t) {
        sgemm_kernel<<<gState, 256>>>(pA, pH,  pY,  BH);   // A @ h
        gate_kernel<<<NN, 256>>>(src, t);
        sgemm_kernel<<<gState, 256>>>(pA, pZH, pY2, BH);   // A @ (z*h)
        update_kernel<<<NN, 256>>>(src, t);
    }

    out_kernel<<<(BB*NN)/256, 256>>>(conv_W, conv_b, out);
}

// round 14
// speedup vs baseline: 1.5791x; 1.5791x over previous
#include <cuda_runtime.h>
#include <cuda_bf16.h>
#include <cstdint>
#include <math.h>

// Shapes (fixed by the problem)
#define NN 2048      // nodes
#define BB 32        // batch
#define TT 12        // time steps
#define DD 10        // embed dim
#define HH 32        // hidden
#define CH 33        // C + H
#define OG 64        // 2H (gate out)
#define BH (BB*HH)       // 1024 columns for state GEMMs
#define NCS (BB*TT)      // 384 columns for source GEMM
#define WGSZ (2*CH*OG)   // 4224
#define WUSZ (2*CH*HH)   // 2112

// ---------------- device scratch (static: allocation-free contract) ----------------
__device__ __nv_bfloat16 g_Ah [NN*NN];    // adjacency hi                8.4 MB
__device__ __nv_bfloat16 g_Al [NN*NN];    // adjacency lo                8.4 MB
__device__ float g_Wg  [NN*WGSZ];         // per-node gate weights      34.6 MB
__device__ float g_bg  [NN*OG];
__device__ float g_Wu  [NN*WUSZ];         // per-node update weights    17.3 MB
__device__ float g_bu  [NN*HH];
__device__ __nv_bfloat16 g_Xsh[NN*NCS];   // src transposed hi
__device__ __nv_bfloat16 g_Xsl[NN*NCS];   // src transposed lo
__device__ float g_AX  [NN*NCS];          // A @ src (fp32)
__device__ float g_H   [NN*BH];           // state fp32 [n][b*32+h]
__device__ __nv_bfloat16 g_Hh [NN*BH];    // state hi
__device__ __nv_bfloat16 g_Hl [NN*BH];    // state lo
__device__ float g_Y   [NN*BH];           // A @ H
__device__ __nv_bfloat16 g_ZHh[NN*BH];    // (z*h) hi
__device__ __nv_bfloat16 g_ZHl[NN*BH];    // (z*h) lo
__device__ float g_Y2  [NN*BH];           // A @ (z*h)
__device__ float g_R   [NN*BH];           // reset gate r

__device__ __forceinline__ void split2(float x, __nv_bfloat16& hi, __nv_bfloat16& lo) {
    hi = __float2bfloat16(x);
    lo = __float2bfloat16(x - __bfloat162float(hi));
}

// ---------------- A = softmax(relu(E E^T)) : one block per row, split-bf16 out ----------------
__global__ __launch_bounds__(256) void adj_kernel(const float* __restrict__ E) {
    const int n = blockIdx.x;
    const int tid = threadIdx.x;
    __shared__ float sE[DD];
    __shared__ float red[256];
    if (tid < DD) sE[tid] = E[n*DD + tid];
    __syncthreads();

    float v[8];
    float mx = 0.0f;
    #pragma unroll
    for (int p = 0; p < 8; ++p) {
        const int m = tid + p*256;
        float s = 0.f;
        #pragma unroll
        for (int d = 0; d < DD; ++d) s += sE[d] * E[m*DD + d];
        s = fmaxf(s, 0.0f);
        v[p] = s;
        mx = fmaxf(mx, s);
    }
    red[tid] = mx; __syncthreads();
    for (int off = 128; off; off >>= 1) {
        if (tid < off) red[tid] = fmaxf(red[tid], red[tid+off]);
        __syncthreads();
    }
    mx = red[0];
    __syncthreads();
    float sum = 0.f;
    #pragma unroll
    for (int p = 0; p < 8; ++p) { v[p] = expf(v[p] - mx); sum += v[p]; }
    red[tid] = sum; __syncthreads();
    for (int off = 128; off; off >>= 1) {
        if (tid < off) red[tid] += red[tid+off];
        __syncthreads();
    }
    const float inv = 1.0f / red[0];
    #pragma unroll
    for (int p = 0; p < 8; ++p) {
        const float a = v[p] * inv;
        __nv_bfloat16 hi, lo; split2(a, hi, lo);
        g_Ah[n*NN + tid + p*256] = hi;
        g_Al[n*NN + tid + p*256] = lo;
    }
}

// ---------------- out[n*R + r] = sum_d E[n,d] * pool[d*R + r] ----------------
__global__ void expand_kernel(const float* __restrict__ pool, const float* __restrict__ E,
                              float* __restrict__ outp, int R) {
    const int total = NN * R;
    for (int idx = blockIdx.x*blockDim.x + threadIdx.x; idx < total;
         idx += gridDim.x*blockDim.x) {
        const int n = idx / R;
        const int r = idx - n*R;
        float s = 0.f;
        #pragma unroll
        for (int d = 0; d < DD; ++d) s += E[n*DD + d] * pool[d*R + r];
        outp[idx] = s;
    }
}

// ---------------- transpose src -> Xs[m][t*32+b] (split bf16) ----------------
__global__ void xpose_kernel(const float* __restrict__ src) {
    const int total = NN * NCS;
    for (int idx = blockIdx.x*blockDim.x + threadIdx.x; idx < total;
         idx += gridDim.x*blockDim.x) {
        const int m = idx / NCS;
        const int j = idx - m*NCS;
        const int t = j >> 5;
        const int b = j & 31;
        const float x = src[(b*TT + t)*NN + m];
        __nv_bfloat16 hi, lo; split2(x, hi, lo);
        g_Xsh[idx] = hi; g_Xsl[idx] = lo;
    }
}

// ---------------- zero H (fp32 + split), Y, Y2 ----------------
__global__ void zero3_kernel() {
    const int total = NN*BH;
    const __nv_bfloat16 z = __float2bfloat16(0.f);
    for (int i = blockIdx.x*blockDim.x + threadIdx.x; i < total;
         i += gridDim.x*blockDim.x) {
        g_H[i] = 0.f; g_Y[i] = 0.f; g_Y2[i] = 0.f;
        g_Hh[i] = z; g_Hl[i] = z;
    }
}

// ---------------- tensor-core split-bf16 GEMM ----------------
// C[2048 x ncols](fp32) = (Ah+Al)[2048x2048] @ (Bh+Bl)[2048 x ncols]
// 3-product scheme: Ah*Bh + Ah*Bl + Al*Bh (lo*lo dropped, ~1e-5 rel err)
// Block tile 128x128, BK=16, 256 threads (8 warps, 4x2), warp tile 32x64.
__device__ __forceinline__ uint32_t smem_u32(const void* p) {
    return (uint32_t)__cvta_generic_to_shared(p);
}
__device__ __forceinline__ void ldsm4(uint32_t r[4], uint32_t addr) {
    asm volatile("ldmatrix.sync.aligned.m8n8.x4.shared.b16 {%0,%1,%2,%3}, [%4];"
        : "=r"(r[0]), "=r"(r[1]), "=r"(r[2]), "=r"(r[3]) : "r"(addr));
}
__device__ __forceinline__ void ldsm2t(uint32_t r[2], uint32_t addr) {
    asm volatile("ldmatrix.sync.aligned.m8n8.x2.trans.shared.b16 {%0,%1}, [%2];"
        : "=r"(r[0]), "=r"(r[1]) : "r"(addr));
}
__device__ __forceinline__ void mma16816(float c[4], const uint32_t a[4], const uint32_t b[2]) {
    asm volatile("mma.sync.aligned.m16n8k16.row.col.f32.bf16.bf16.f32 "
        "{%0,%1,%2,%3}, {%4,%5,%6,%7}, {%8,%9}, {%0,%1,%2,%3};"
        : "+f"(c[0]), "+f"(c[1]), "+f"(c[2]), "+f"(c[3])
        : "r"(a[0]), "r"(a[1]), "r"(a[2]), "r"(a[3]), "r"(b[0]), "r"(b[1]));
}

__global__ __launch_bounds__(256) void bgemm_kernel(
    const __nv_bfloat16* __restrict__ Ah, const __nv_bfloat16* __restrict__ Al,
    const __nv_bfloat16* __restrict__ Bh, const __nv_bfloat16* __restrict__ Bl,
    float* __restrict__ C, int ncols)
{
    __shared__ __align__(16) __nv_bfloat16 sAh[128][24];   // 16 data + 8 pad (48B rows)
    __shared__ __align__(16) __nv_bfloat16 sAl[128][24];
    __shared__ __align__(16) __nv_bfloat16 sBh[16][136];   // 128 data + 8 pad (272B rows)
    __shared__ __align__(16) __nv_bfloat16 sBl[16][136];

    const int tid  = threadIdx.x;
    const int bm   = blockIdx.y * 128;
    const int bn   = blockIdx.x * 128;
    const int warp = tid >> 5, lane = tid & 31;
    const int wm   = warp >> 1, wn = warp & 1;

    // gmem staging: A = 128 rows x 16 cols (2 x uint4 per row); B = 16 rows x 128 cols
    const int ar = tid >> 1,  ac = (tid & 1)  * 8;
    const int br = tid >> 4,  bc = (tid & 15) * 8;
    const __nv_bfloat16* gAh = Ah + (size_t)(bm + ar)*NN + ac;
    const __nv_bfloat16* gAl = Al + (size_t)(bm + ar)*NN + ac;
    const __nv_bfloat16* gBh = Bh + (size_t)br*ncols + bn + bc;
    const __nv_bfloat16* gBl = Bl + (size_t)br*ncols + bn + bc;

    uint4 pah = *(const uint4*)gAh;
    uint4 pal = *(const uint4*)gAl;
    uint4 pbh = *(const uint4*)gBh;
    uint4 pbl = *(const uint4*)gBl;

    float acc[2][8][4] = {};

    // ldmatrix lane addressing
    const int lr  = lane & 7;
    const int grp = lane >> 3;
    const int a_row = wm*32 + (grp & 1)*8 + lr;   // + mt*16 later
    const int a_col = (grp >> 1)*8;
    const uint32_t aAh = smem_u32(&sAh[a_row][a_col]);
    const uint32_t aAl = smem_u32(&sAl[a_row][a_col]);
    const int b_row = lane & 15;
    const uint32_t aBh = smem_u32(&sBh[b_row][wn*64]);
    const uint32_t aBl = smem_u32(&sBl[b_row][wn*64]);

    for (int k0 = 0; k0 < NN; k0 += 16) {
        *(uint4*)&sAh[ar][ac] = pah;
        *(uint4*)&sAl[ar][ac] = pal;
        *(uint4*)&sBh[br][bc] = pbh;
        *(uint4*)&sBl[br][bc] = pbl;
        __syncthreads();

        if (k0 + 16 < NN) {
            pah = *(const uint4*)(gAh + k0 + 16);
            pal = *(const uint4*)(gAl + k0 + 16);
            pbh = *(const uint4*)(gBh + (size_t)(k0 + 16)*ncols);
            pbl = *(const uint4*)(gBl + (size_t)(k0 + 16)*ncols);
        }

        uint32_t fah[2][4], fal[2][4];
        #pragma unroll
        for (int mt = 0; mt < 2; ++mt) {
            ldsm4(fah[mt], aAh + mt*16*48);   // 16 rows * 48B
            ldsm4(fal[mt], aAl + mt*16*48);
        }
        #pragma unroll
        for (int nt = 0; nt < 8; ++nt) {
            uint32_t fbh[2], fbl[2];
            ldsm2t(fbh, aBh + nt*16);         // 8 cols * 2B
            ldsm2t(fbl, aBl + nt*16);
            #pragma unroll
            for (int mt = 0; mt < 2; ++mt) {
                mma16816(acc[mt][nt], fah[mt], fbh);   // hi*hi
                mma16816(acc[mt][nt], fah[mt], fbl);   // hi*lo
                mma16816(acc[mt][nt], fal[mt], fbh);   // lo*hi
            }
        }
        __syncthreads();
    }

    // epilogue
    const int crow = bm + wm*32 + (lane >> 2);
    const int ccol = bn + wn*64 + (lane & 3)*2;
    #pragma unroll
    for (int mt = 0; mt < 2; ++mt) {
        #pragma unroll
        for (int nt = 0; nt < 8; ++nt) {
            const int r = crow + mt*16;
            const int c = ccol + nt*8;
            float2 v0 = make_float2(acc[mt][nt][0], acc[mt][nt][1]);
            float2 v1 = make_float2(acc[mt][nt][2], acc[mt][nt][3]);
            *(float2*)&C[(size_t)r*ncols + c]       = v0;
            *(float2*)&C[(size_t)(r+8)*ncols + c]   = v1;
        }
    }
}

// ---------------- gate kernel: one block per node ----------------
// zr = sigmoid( bg[n] + sum_ii xs[ii] * Wg[n][ii][o] )
// writes ZH = z*h (split bf16) and R = r (fp32)
__global__ __launch_bounds__(256) void gate_kernel(const float* __restrict__ src, int t) {
    const int n = blockIdx.x;
    const int tid = threadIdx.x;
    __shared__ float sW[WGSZ];
    __shared__ float sxs[66*33];
    __shared__ float sbg[OG];

    const float* Wg = g_Wg + n*WGSZ;
    for (int i = tid; i < WGSZ; i += 256) sW[i] = Wg[i];
    if (tid < OG) sbg[tid] = g_bg[n*OG + tid];
    if (tid < BB) {
        sxs[0*33 + tid]  = src[(tid*TT + t)*NN + n];
        sxs[33*33 + tid] = g_AX[n*NCS + t*BB + tid];
    }
    for (int j = tid; j < BH; j += 256) {
        const int b = j >> 5, hh = j & 31;
        sxs[(1+hh)*33 + b]  = g_H[n*BH + j];
        sxs[(34+hh)*33 + b] = g_Y[n*BH + j];
    }
    __syncthreads();

    const int o  = tid & 63;
    const int bg = tid >> 6;
    float acc[8];
    #pragma unroll
    for (int p = 0; p < 8; ++p) acc[p] = sbg[o];
    #pragma unroll 2
    for (int ii = 0; ii < 66; ++ii) {
        const float w = sW[ii*64 + o];
        #pragma unroll
        for (int p = 0; p < 8; ++p)
            acc[p] = fmaf(w, sxs[ii*33 + bg + p*4], acc[p]);
    }
    #pragma unroll
    for (int p = 0; p < 8; ++p) {
        const int b = bg + p*4;
        const float v = 1.0f / (1.0f + expf(-acc[p]));
        if (o < HH) {
            const float zh = v * sxs[(1+o)*33 + b];
            const int idx = n*BH + b*HH + o;
            __nv_bfloat16 hi, lo; split2(zh, hi, lo);
            g_ZHh[idx] = hi; g_ZHl[idx] = lo;
        } else {
            g_R[n*BH + b*HH + (o - HH)] = v;
        }
    }
}

// ---------------- update kernel: one block per node ----------------
__global__ __launch_bounds__(256) void update_kernel(const float* __restrict__ src, int t) {
    const int n = blockIdx.x;
    const int tid = threadIdx.x;
    __shared__ float sW[WUSZ];
    __shared__ float sxu[66*33];
    __shared__ float sbu[HH];

    const float* Wu = g_Wu + n*WUSZ;
    for (int i = tid; i < WUSZ; i += 256) sW[i] = Wu[i];
    if (tid < HH) sbu[tid] = g_bu[n*HH + tid];
    if (tid < BB) {
        sxu[0*33 + tid]  = src[(tid*TT + t)*NN + n];
        sxu[33*33 + tid] = g_AX[n*NCS + t*BB + tid];
    }
    for (int j = tid; j < BH; j += 256) {
        const int b = j >> 5, hh = j & 31;
        sxu[(1+hh)*33 + b]  = __bfloat162float(g_ZHh[n*BH + j]) + __bfloat162float(g_ZHl[n*BH + j]);
        sxu[(34+hh)*33 + b] = g_Y2[n*BH + j];
    }
    __syncthreads();

    const int o  = tid & 31;
    const int bg = tid >> 5;
    float acc[4];
    #pragma unroll
    for (int p = 0; p < 4; ++p) acc[p] = sbu[o];
    #pragma unroll 2
    for (int ii = 0; ii < 66; ++ii) {
        const float w = sW[ii*32 + o];
        #pragma unroll
        for (int p = 0; p < 4; ++p)
            acc[p] = fmaf(w, sxu[ii*33 + bg + p*8], acc[p]);
    }
    #pragma unroll
    for (int p = 0; p < 4; ++p) {
        const int b = bg + p*8;
        const float hc = tanhf(acc[p]);
        const int idx = n*BH + b*HH + o;
        const float r = g_R[idx];
        const float h = g_H[idx];
        const float hn = r*h + (1.0f - r)*hc;
        g_H[idx] = hn;
        __nv_bfloat16 hi, lo; split2(hn, hi, lo);
        g_Hh[idx] = hi; g_Hl[idx] = lo;
    }
}

// ---------------- output ----------------
__global__ __launch_bounds__(256) void out_kernel(const float* __restrict__ convW,
                                                  const float* __restrict__ convb,
                                                  float* __restrict__ out) {
    __shared__ float sw[TT*HH];
    __shared__ float sb[TT];
    const int tid = threadIdx.x;
    for (int i = tid; i < TT*HH; i += 256) sw[i] = convW[i];
    if (tid < TT) sb[tid] = convb[tid];
    __syncthreads();

    const int idx = blockIdx.x*256 + tid;
    const int b = idx >> 11;
    const int n = idx & (NN-1);
    float hreg[HH];
    const float4* hp = (const float4*)(g_H + n*BH + b*HH);
    #pragma unroll
    for (int q = 0; q < 8; ++q) {
        const float4 v = hp[q];
        hreg[q*4+0] = v.x; hreg[q*4+1] = v.y; hreg[q*4+2] = v.z; hreg[q*4+3] = v.w;
    }
    #pragma unroll
    for (int tt = 0; tt < TT; ++tt) {
        float s = sb[tt];
        #pragma unroll
        for (int h = 0; h < HH; ++h) s = fmaf(hreg[h], sw[tt*HH + h], s);
        out[(b*NN + n)*TT + tt] = s;
    }
}

// ---------------- launcher ----------------
extern "C" void kernel_launch(void* const* d_in, const int* in_sizes, int n_in,
                              void* d_out, int out_size) {
    (void)in_sizes; (void)n_in; (void)out_size;
    const float* src    = (const float*)d_in[0];
    const float* E      = (const float*)d_in[1];
    const float* gate_W = (const float*)d_in[2];
    const float* gate_b = (const float*)d_in[3];
    const float* upd_W  = (const float*)d_in[4];
    const float* upd_b  = (const float*)d_in[5];
    const float* conv_W = (const float*)d_in[6];
    const float* conv_b = (const float*)d_in[7];
    float* out = (float*)d_out;

    __nv_bfloat16 *pAh, *pAl, *pXsh, *pXsl, *pHh, *pHl, *pZHh, *pZHl;
    float *pAX, *pY, *pY2;
    float *pWg, *pbg, *pWu, *pbu;
    cudaGetSymbolAddress((void**)&pAh,  g_Ah);
    cudaGetSymbolAddress((void**)&pAl,  g_Al);
    cudaGetSymbolAddress((void**)&pXsh, g_Xsh);
    cudaGetSymbolAddress((void**)&pXsl, g_Xsl);
    cudaGetSymbolAddress((void**)&pHh,  g_Hh);
    cudaGetSymbolAddress((void**)&pHl,  g_Hl);
    cudaGetSymbolAddress((void**)&pZHh, g_ZHh);
    cudaGetSymbolAddress((void**)&pZHl, g_ZHl);
    cudaGetSymbolAddress((void**)&pAX,  g_AX);
    cudaGetSymbolAddress((void**)&pY,   g_Y);
    cudaGetSymbolAddress((void**)&pY2,  g_Y2);
    cudaGetSymbolAddress((void**)&pWg,  g_Wg);
    cudaGetSymbolAddress((void**)&pbg,  g_bg);
    cudaGetSymbolAddress((void**)&pWu,  g_Wu);
    cudaGetSymbolAddress((void**)&pbu,  g_bu);

    // --- time-invariant precompute ---
    adj_kernel<<<NN, 256>>>(E);
    expand_kernel<<<2048, 256>>>(gate_W, E, pWg, WGSZ);
    expand_kernel<<<256,  256>>>(gate_b, E, pbg, OG);
    expand_kernel<<<2048, 256>>>(upd_W,  E, pWu, WUSZ);
    expand_kernel<<<256,  256>>>(upd_b,  E, pbu, HH);
    xpose_kernel<<<1024, 256>>>(src);
    zero3_kernel<<<2048, 256>>>();

    dim3 gSrc(NCS/128, NN/128);    // (3, 16)
    bgemm_kernel<<<gSrc, 256>>>(pAh, pAl, pXsh, pXsl, pAX, NCS);  // AX = A @ src

    // --- t = 0: state is zero, so A@H = A@ZH = 0 (pre-zeroed); skip both GEMMs ---
    gate_kernel<<<NN, 256>>>(src, 0);
    update_kernel<<<NN, 256>>>(src, 0);

    dim3 gState(BH/128, NN/128);   // (8, 16)
    for (int t = 1; t < TT; ++t) {
        bgemm_kernel<<<gState, 256>>>(pAh, pAl, pHh,  pHl,  pY,  BH);   // A @ h
        gate_kernel<<<NN, 256>>>(src, t);
        bgemm_kernel<<<gState, 256>>>(pAh, pAl, pZHh, pZHl, pY2, BH);   // A @ (z*h)
        update_kernel<<<NN, 256>>>(src, t);
    }

    out_kernel<<<(BB*NN)/256, 256>>>(conv_W, conv_b, out);
}